// round 16
// baseline (speedup 1.0000x reference)
#include <cuda_runtime.h>
#include <cuda_bf16.h>
#include <math.h>

#define N_NODES  50000
#define N_EDGES  800000
#define NODE_D   128
#define EDGE_D   100
#define EMB_D    92
#define N_GRAPHS 256
#define N_CONV   3
#define FC_D     128

#define DELTA    (6.0f / 99.0f)
#define N_T      1800
#define H_T      (DELTA / 16.0f)
#define NTF      (16 * (N_T - 1))          // 28784 fine rows
#define H_F      (DELTA / 256.0f)

#define SB    256
#define SGRID ((N_NODES + SB - 1) / SB)
#define GHGRID ((N_NODES + 7) / 8)

// ---------------- scratch (device globals) ----------------
__device__ float g_embt[100 * NODE_D];
__device__ float g_x[N_NODES * NODE_D];
__device__ __nv_bfloat16 g_xh[N_NODES * NODE_D];
__device__ float g_A[N_NODES * 256];
__device__ __nv_bfloat16 g_Bh[N_NODES * 256];         // INTERLEAVED: [z1[0],z2[0],z1[1],z2[1],...]
__device__ uint2 g_Wp[N_CONV][8 * 64 * 32];
__device__ float g_tab[N_CONV][N_T * 256];            // logical layout
__device__ __nv_bfloat16 g_tabf[N_CONV][(size_t)NTF * 256];  // INTERLEAVED like g_Bh
__device__ int   g_deg[N_NODES];
__device__ int   g_off[N_NODES];
__device__ int   g_rowstart[N_NODES + 1];
__device__ int   g_bsum[SGRID];
__device__ uint2 g_edge[N_EDGES];
__device__ float g_pool[N_GRAPHS * NODE_D];
__device__ float g_cnt[N_GRAPHS];

// ---------------- fast math helpers ----------------
__device__ __forceinline__ float softplusf(float x) {
    return fmaxf(x, 0.f) + __logf(1.f + __expf(-fabsf(x)));
}
__device__ __forceinline__ float bflo(unsigned u) { return __uint_as_float(u << 16); }
__device__ __forceinline__ float bfhi(unsigned u) { return __uint_as_float(u & 0xffff0000u); }

__device__ __forceinline__ unsigned bf2add(unsigned a, unsigned b) {
    unsigned r;
    asm("add.rn.bf16x2 %0, %1, %2;" : "=r"(r) : "r"(a), "r"(b));
    return r;
}

// packed f16x2 sigmoid via tanh.approx.f16x2: sigma(x) = 0.5*tanh(x/2)+0.5
__device__ __forceinline__ float2 sigmoid2(float x, float y) {
    unsigned h;
    asm("cvt.rn.f16x2.f32 %0, %1, %2;" : "=r"(h) : "f"(y * 0.5f), "f"(x * 0.5f));
    asm("tanh.approx.f16x2 %0, %0;" : "+r"(h));
    float tx, ty;
    asm("{ .reg .b16 lo, hi; mov.b32 {lo, hi}, %2; cvt.f32.f16 %0, lo; cvt.f32.f16 %1, hi; }"
        : "=f"(tx), "=f"(ty) : "r"(h));
    return make_float2(fmaf(0.5f, tx, 0.5f), fmaf(0.5f, ty, 0.5f));
}

__device__ __forceinline__ void mma_bf16(float* c, const unsigned* a, uint2 b) {
    asm volatile(
        "mma.sync.aligned.m16n8k16.row.col.f32.bf16.bf16.f32 "
        "{%0,%1,%2,%3}, {%4,%5,%6,%7}, {%8,%9}, {%0,%1,%2,%3};"
        : "+f"(c[0]), "+f"(c[1]), "+f"(c[2]), "+f"(c[3])
        : "r"(a[0]), "r"(a[1]), "r"(a[2]), "r"(a[3]), "r"(b.x), "r"(b.y));
}

// per-edge message accumulate (interleaved packed operands)
__device__ __forceinline__ void edge_accum(const float4& a1, const float4& a2,
                                           uint4 bu, uint4 tu, float4& acc) {
    unsigned s0 = bf2add(bu.x, tu.x);
    unsigned s1 = bf2add(bu.y, tu.y);
    unsigned s2 = bf2add(bu.z, tu.z);
    unsigned s3 = bf2add(bu.w, tu.w);
    float4 z1, z2;
    z1.x = a1.x + bflo(s0); z2.x = a2.x + bfhi(s0);
    z1.y = a1.y + bflo(s1); z2.y = a2.y + bfhi(s1);
    z1.z = a1.z + bflo(s2); z2.z = a2.z + bfhi(s2);
    z1.w = a1.w + bflo(s3); z2.w = a2.w + bfhi(s3);
    float2 sA = sigmoid2(z1.x, z1.y);
    float2 sB = sigmoid2(z1.z, z1.w);
    acc.x = fmaf(sA.x, softplusf(z2.x), acc.x);
    acc.y = fmaf(sA.y, softplusf(z2.y), acc.y);
    acc.z = fmaf(sB.x, softplusf(z2.z), acc.z);
    acc.w = fmaf(sB.y, softplusf(z2.w), acc.w);
}

// ---------------- fused setup: zero + emb_table + graph_count ----------------
__global__ void setup_kernel(const float* __restrict__ emb,
                             const float* __restrict__ W,
                             const float* __restrict__ b,
                             const int* __restrict__ batch) {
    __shared__ float er[EMB_D];
    int bx = blockIdx.x;
    if (bx < SGRID) {
        int i = bx * SB + threadIdx.x;
        if (i < N_NODES) g_deg[i] = 0;
        if (i < N_GRAPHS * NODE_D) g_pool[i] = 0.f;
    } else if (bx < SGRID + 100) {
        int r = bx - SGRID;
        if (threadIdx.x < EMB_D) er[threadIdx.x] = emb[r * EMB_D + threadIdx.x];
        __syncthreads();
        int c = threadIdx.x;
        if (c < NODE_D) {
            float acc = b[c];
#pragma unroll 4
            for (int k = 0; k < EMB_D; k++) acc += er[k] * W[k * NODE_D + c];
            g_embt[r * NODE_D + c] = acc;
        }
    } else {
        int g = threadIdx.x;
        if (g < N_GRAPHS) {
            int lo = 0, hi = N_NODES;
            while (lo < hi) { int m = (lo + hi) >> 1; if (batch[m] < g) lo = m + 1; else hi = m; }
            int a = lo;
            lo = 0; hi = N_NODES;
            while (lo < hi) { int m = (lo + hi) >> 1; if (batch[m] <= g) lo = m + 1; else hi = m; }
            g_cnt[g] = (float)(lo - a);
        }
    }
}

// ---------------- fused: x0 gather + dst histogram ----------------
__global__ void gather_hist_kernel(const int* __restrict__ z,
                                   const int* __restrict__ dst) {
    int n = blockIdx.x * 8 + (threadIdx.x >> 5);
    int lane = threadIdx.x & 31;
    if (n < N_NODES) {
        int zi = z[n];                       // same addr per warp -> broadcast
        float4 v = ((const float4*)g_embt)[zi * 32 + lane];
        ((float4*)g_x)[(size_t)n * 32 + lane] = v;
        __nv_bfloat162 p0 = __floats2bfloat162_rn(v.x, v.y);
        __nv_bfloat162 p1 = __floats2bfloat162_rn(v.z, v.w);
        ((uint2*)g_xh)[(size_t)n * 32 + lane] = make_uint2(*(unsigned*)&p0, *(unsigned*)&p1);
    }
    int gid = blockIdx.x * blockDim.x + threadIdx.x;
    if (gid < N_EDGES) atomicAdd(&g_deg[dst[gid]], 1);
}

// ---------------- scan passes ----------------
__global__ void scan_pass1() {
    __shared__ int ws[8];
    int i = blockIdx.x * SB + threadIdx.x;
    int v = (i < N_NODES) ? g_deg[i] : 0;
#pragma unroll
    for (int off = 16; off > 0; off >>= 1) v += __shfl_xor_sync(0xffffffffu, v, off);
    if ((threadIdx.x & 31) == 0) ws[threadIdx.x >> 5] = v;
    __syncthreads();
    if (threadIdx.x == 0) {
        int s = 0;
#pragma unroll
        for (int w = 0; w < 8; w++) s += ws[w];
        g_bsum[blockIdx.x] = s;
    }
}

__global__ void scan_pass2() {
    __shared__ int sm[SB];
    int t = threadIdx.x;
    int v = (t < SGRID) ? g_bsum[t] : 0;
    sm[t] = v;
    __syncthreads();
#pragma unroll
    for (int off = 1; off < SB; off <<= 1) {
        int u = (t >= off) ? sm[t - off] : 0;
        __syncthreads();
        sm[t] += u;
        __syncthreads();
    }
    if (t < SGRID) g_bsum[t] = sm[t] - v;
}

__global__ void scan_pass3() {
    __shared__ int sm[SB];
    int t = threadIdx.x;
    int i = blockIdx.x * SB + t;
    int v = (i < N_NODES) ? g_deg[i] : 0;
    sm[t] = v;
    __syncthreads();
#pragma unroll
    for (int off = 1; off < SB; off <<= 1) {
        int u = (t >= off) ? sm[t - off] : 0;
        __syncthreads();
        sm[t] += u;
        __syncthreads();
    }
    int ex = g_bsum[blockIdx.x] + sm[t] - v;
    if (i < N_NODES) {
        g_rowstart[i] = ex;
        g_off[i] = ex;
        if (i == N_NODES - 1) g_rowstart[N_NODES] = ex + v;
    }
}

__global__ void scatter_kernel(const float* __restrict__ R,
                               const int* __restrict__ src,
                               const int* __restrict__ dst) {
    int e = blockIdx.x * blockDim.x + threadIdx.x;
    if (e >= N_EDGES) return;
    int s = src[e], d = dst[e];
    float dx = R[s * 3 + 0] - R[d * 3 + 0];
    float dy = R[s * 3 + 1] - R[d * 3 + 1];
    float dz = R[s * 3 + 2] - R[d * 3 + 2];
    float dist = sqrtf(dx * dx + dy * dy + dz * dz);
    int t = (int)(fminf(dist / H_F + 0.5f, (float)(NTF - 1)));
    int pos = atomicAdd(&g_off[d], 1);
    g_edge[pos] = make_uint2((unsigned)s, (unsigned)t);
}

// ---------------- coarse tables, all layers (logical layout) ----------------
__global__ void build_tab_kernel(const float* __restrict__ conv_w) {
    __shared__ float gs[EDGE_D];
    int l = blockIdx.y;
    const float* W3 = conv_w + (size_t)l * 356 * 256 + 256 * 256;
    int t = blockIdx.x;
    float d = (float)t * H_T;
    const float coeff = -0.5f / (DELTA * DELTA);
    if (threadIdx.x < EDGE_D) {
        float u = d - (float)threadIdx.x * DELTA;
        gs[threadIdx.x] = expf(coeff * u * u);
    }
    __syncthreads();
    int c = threadIdx.x;
    float acc = 0.f;
#pragma unroll 4
    for (int k = 0; k < EDGE_D; k++) acc += gs[k] * W3[k * 256 + c];
    g_tab[l][(size_t)t * 256 + c] = acc;
}

// ---------------- expand coarse -> fine bf16 (INTERLEAVED channels) ----------------
__global__ void expand_tab_kernel() {
    int l = blockIdx.y;
    int tf = blockIdx.x;
    int c = threadIdx.x;
    int lc = (c & 1) ? 128 + (c >> 1) : (c >> 1);
    int t = tf >> 4;
    float f = (float)(tf & 15) * (1.f / 16.f);
    float lo = g_tab[l][(size_t)t * 256 + lc];
    float hi = g_tab[l][(size_t)(t + 1) * 256 + lc];
    g_tabf[l][(size_t)tf * 256 + c] = __float2bfloat16(fmaf(f, hi - lo, lo));
}

// ---------------- weight pack (src half column-permuted for interleaved output) ----------------
__global__ void pack_w_kernel(const float* __restrict__ conv_w) {
    int l = blockIdx.y;
    const float* Wl = conv_w + (size_t)l * 356 * 256;
    int idx = blockIdx.x * 256 + threadIdx.x;
    if (idx >= 8 * 64 * 32) return;
    int lane = idx & 31;
    int ntile = (idx >> 5) & 63;
    int kt = idx >> 11;
    int u = lane & 3, c = lane >> 2;
    int n = ntile * 8 + c;
    const float* W = Wl + ((n < 256) ? 0 : 128 * 256);
    int wc;
    if (n < 256) {
        wc = n;
    } else {
        int p = n - 256;
        wc = (p & 1) ? 128 + (p >> 1) : (p >> 1);
    }
    int k = kt * 16 + 2 * u;
    __nv_bfloat162 v0 = __floats2bfloat162_rn(W[(k + 0) * 256 + wc], W[(k + 1) * 256 + wc]);
    __nv_bfloat162 v1 = __floats2bfloat162_rn(W[(k + 8) * 256 + wc], W[(k + 9) * 256 + wc]);
    g_Wp[l][idx] = make_uint2(*(unsigned*)&v0, *(unsigned*)&v1);
}

// ---------------- tensor-core GEMM ----------------
#define TBM 64
__global__ void gemm_mma_kernel(const float* __restrict__ bias, int layer) {
    __shared__ __nv_bfloat16 As[TBM][136];
    int tid = threadIdx.x;
    int m0 = blockIdx.y * TBM;
    int n0 = blockIdx.x * 256;

#pragma unroll
    for (int i = 0; i < 4; i++) {
        int idx = tid + i * 256;
        int r = idx >> 4, cs = idx & 15;
        uint4 v = make_uint4(0, 0, 0, 0);
        if (m0 + r < N_NODES) v = *(const uint4*)(g_xh + (size_t)(m0 + r) * NODE_D + cs * 8);
        *(uint4*)&As[r][cs * 8] = v;
    }
    __syncthreads();

    int wid = tid >> 5, lane = tid & 31;
    int wm = wid >> 2, wn = wid & 3;
    int g = lane >> 2, u = lane & 3;
    int mbase = wm * 32;
    int ntile0 = (n0 + wn * 64) >> 3;
    const uint2* Wp = g_Wp[layer];

    float acc[2][8][4];
#pragma unroll
    for (int a = 0; a < 2; a++)
#pragma unroll
        for (int b = 0; b < 8; b++)
#pragma unroll
            for (int c = 0; c < 4; c++) acc[a][b][c] = 0.f;

#pragma unroll
    for (int kt = 0; kt < 8; kt++) {
        int k0 = kt * 16;
        unsigned afr[2][4];
#pragma unroll
        for (int mf = 0; mf < 2; mf++) {
            int rb = mbase + mf * 16;
            afr[mf][0] = *(unsigned*)&As[rb + g][k0 + 2 * u];
            afr[mf][1] = *(unsigned*)&As[rb + g + 8][k0 + 2 * u];
            afr[mf][2] = *(unsigned*)&As[rb + g][k0 + 8 + 2 * u];
            afr[mf][3] = *(unsigned*)&As[rb + g + 8][k0 + 8 + 2 * u];
        }
        uint2 bfr[8];
#pragma unroll
        for (int j = 0; j < 8; j++)
            bfr[j] = Wp[(kt * 64 + ntile0 + j) * 32 + lane];
#pragma unroll
        for (int mf = 0; mf < 2; mf++)
#pragma unroll
            for (int j = 0; j < 8; j++)
                mma_bf16(acc[mf][j], afr[mf], bfr[j]);
    }

#pragma unroll
    for (int mf = 0; mf < 2; mf++) {
        int row0 = m0 + mbase + mf * 16 + g;
#pragma unroll
        for (int j = 0; j < 8; j++) {
            int col = n0 + wn * 64 + j * 8 + 2 * u;
            float* ac = acc[mf][j];
            if (n0 == 0) {
                float2 bv = *(const float2*)(bias + col);
                if (row0 < N_NODES)
                    *(float2*)(g_A + (size_t)row0 * 256 + col) =
                        make_float2(ac[0] + bv.x, ac[1] + bv.y);
                if (row0 + 8 < N_NODES)
                    *(float2*)(g_A + (size_t)(row0 + 8) * 256 + col) =
                        make_float2(ac[2] + bv.x, ac[3] + bv.y);
            } else {
                int cb = col - 256;
                if (row0 < N_NODES) {
                    __nv_bfloat162 p = __floats2bfloat162_rn(ac[0], ac[1]);
                    *(unsigned*)(g_Bh + (size_t)row0 * 256 + cb) = *(unsigned*)&p;
                }
                if (row0 + 8 < N_NODES) {
                    __nv_bfloat162 p = __floats2bfloat162_rn(ac[2], ac[3]);
                    *(unsigned*)(g_Bh + (size_t)(row0 + 8) * 256 + cb) = *(unsigned*)&p;
                }
            }
        }
    }
}

// ---------------- fused edge aggregation: 2 warps SPLIT one node's edges ----------------
template <bool LAST>
__global__ void __launch_bounds__(64) edge_agg_kernel(const float* __restrict__ lng,
                                                      const float* __restrict__ lnb,
                                                      const int* __restrict__ batch,
                                                      int layer) {
    __shared__ float4 sacc[32];
    int n = blockIdx.x;
    int wid = threadIdx.x >> 5;
    int lane = threadIdx.x & 31;

    int row = g_rowstart[n];
    int end = g_rowstart[n + 1];

    const float4* Arow = (const float4*)(g_A + (size_t)n * 256);
    float4 a1 = Arow[lane];
    float4 a2 = Arow[32 + lane];
    const __nv_bfloat16* tabf = g_tabf[layer];
    int loff = 8 * lane;                    // 16B per lane

    float4 acc = make_float4(0.f, 0.f, 0.f, 0.f);

    // warp `wid` handles edges row+wid, row+wid+2, ... (stride 2, unroll 2)
    int e = row + wid;
    for (; e + 2 < end; e += 4) {
        uint2 ed0 = __ldg(&g_edge[e]);
        uint2 ed1 = __ldg(&g_edge[e + 2]);
        uint4 b0 = __ldg((const uint4*)(g_Bh + (size_t)ed0.x * 256 + loff));
        uint4 t0 = __ldg((const uint4*)(tabf + (size_t)ed0.y * 256 + loff));
        uint4 b1 = __ldg((const uint4*)(g_Bh + (size_t)ed1.x * 256 + loff));
        uint4 t1 = __ldg((const uint4*)(tabf + (size_t)ed1.y * 256 + loff));
        edge_accum(a1, a2, b0, t0, acc);
        edge_accum(a1, a2, b1, t1, acc);
    }
    for (; e < end; e += 2) {
        uint2 ed = __ldg(&g_edge[e]);
        uint4 bu = __ldg((const uint4*)(g_Bh + (size_t)ed.x * 256 + loff));
        uint4 tu = __ldg((const uint4*)(tabf + (size_t)ed.y * 256 + loff));
        edge_accum(a1, a2, bu, tu, acc);
    }

    // combine the two warps' partials
    if (wid == 1) sacc[lane] = acc;
    __syncthreads();
    if (wid == 1) return;
    float4 p = sacc[lane];
    acc.x += p.x; acc.y += p.y; acc.z += p.z; acc.w += p.w;

    float s  = acc.x + acc.y + acc.z + acc.w;
    float ss = acc.x * acc.x + acc.y * acc.y + acc.z * acc.z + acc.w * acc.w;
#pragma unroll
    for (int off = 16; off > 0; off >>= 1) {
        s  += __shfl_xor_sync(0xffffffffu, s, off);
        ss += __shfl_xor_sync(0xffffffffu, ss, off);
    }
    float mu = s * (1.f / 128.f);
    float var = ss * (1.f / 128.f) - mu * mu;
    float rinv = rsqrtf(var + 1e-5f);

    float4 gg = ((const float4*)lng)[lane];
    float4 bb = ((const float4*)lnb)[lane];
    float4 xo = ((float4*)g_x)[(size_t)n * 32 + lane];
    float4 o;
    o.x = softplusf((acc.x - mu) * rinv * gg.x + bb.x + xo.x);
    o.y = softplusf((acc.y - mu) * rinv * gg.y + bb.y + xo.y);
    o.z = softplusf((acc.z - mu) * rinv * gg.z + bb.z + xo.z);
    o.w = softplusf((acc.w - mu) * rinv * gg.w + bb.w + xo.w);

    if (!LAST) {
        ((float4*)g_x)[(size_t)n * 32 + lane] = o;
        __nv_bfloat162 p0 = __floats2bfloat162_rn(o.x, o.y);
        __nv_bfloat162 p1 = __floats2bfloat162_rn(o.z, o.w);
        ((uint2*)g_xh)[(size_t)n * 32 + lane] = make_uint2(*(unsigned*)&p0, *(unsigned*)&p1);
    } else {
        int b = batch[n];                   // same addr per warp -> broadcast
        float* base = g_pool + (size_t)b * NODE_D + 4 * lane;
        atomicAdd(base + 0, o.x);
        atomicAdd(base + 1, o.y);
        atomicAdd(base + 2, o.z);
        atomicAdd(base + 3, o.w);
    }
}

// ---------------- head MLP ----------------
__global__ void head_kernel(const float* __restrict__ cfc_w, const float* __restrict__ cfc_b,
                            const float* __restrict__ fc_w,  const float* __restrict__ fc_b,
                            const float* __restrict__ out_w, const float* __restrict__ out_b,
                            float* __restrict__ out) {
    __shared__ float h0[FC_D], h1[FC_D];
    __shared__ float red[4];
    int g = blockIdx.x, c = threadIdx.x;
    float cn = fmaxf(g_cnt[g], 1.f);
    h0[c] = g_pool[(size_t)g * NODE_D + c] / cn;
    __syncthreads();
    float acc = cfc_b[c];
#pragma unroll 4
    for (int k = 0; k < NODE_D; k++) acc += h0[k] * cfc_w[k * FC_D + c];
    h1[c] = softplusf(acc);
    __syncthreads();
    acc = fc_b[c];
#pragma unroll 4
    for (int k = 0; k < FC_D; k++) acc += h1[k] * fc_w[k * FC_D + c];
    h0[c] = softplusf(acc);
    __syncthreads();
    acc = fc_b[FC_D + c];
#pragma unroll 4
    for (int k = 0; k < FC_D; k++) acc += h0[k] * fc_w[FC_D * FC_D + k * FC_D + c];
    h1[c] = softplusf(acc);
    __syncthreads();
    float p = h1[c] * out_w[c];
#pragma unroll
    for (int off = 16; off > 0; off >>= 1) p += __shfl_xor_sync(0xffffffffu, p, off);
    if ((c & 31) == 0) red[c >> 5] = p;
    __syncthreads();
    if (c == 0) out[g] = red[0] + red[1] + red[2] + red[3] + out_b[0];
}

// ---------------- launch ----------------
extern "C" void kernel_launch(void* const* d_in, const int* in_sizes, int n_in,
                              void* d_out, int out_size) {
    const int*   z         = (const int*)d_in[0];
    const float* R         = (const float*)d_in[1];
    const int*   ei        = (const int*)d_in[2];
    const int*   batch     = (const int*)d_in[3];
    const float* embedding = (const float*)d_in[4];
    const float* emb_w     = (const float*)d_in[5];
    const float* emb_b     = (const float*)d_in[6];
    const float* conv_w    = (const float*)d_in[7];
    const float* conv_b    = (const float*)d_in[8];
    const float* ln_g      = (const float*)d_in[9];
    const float* ln_b      = (const float*)d_in[10];
    const float* cfc_w     = (const float*)d_in[11];
    const float* cfc_b     = (const float*)d_in[12];
    const float* fc_w      = (const float*)d_in[13];
    const float* fc_b      = (const float*)d_in[14];
    const float* out_w     = (const float*)d_in[15];
    const float* out_b     = (const float*)d_in[16];
    float* out = (float*)d_out;

    const int* src = ei;
    const int* dst = ei + N_EDGES;

    static cudaStream_t s_prep = nullptr;
    static cudaEvent_t ev_fork = nullptr, ev_join = nullptr;
    if (s_prep == nullptr) {
        cudaStreamCreateWithFlags(&s_prep, cudaStreamNonBlocking);
        cudaEventCreateWithFlags(&ev_fork, cudaEventDisableTiming);
        cudaEventCreateWithFlags(&ev_join, cudaEventDisableTiming);
    }

    // fork: weight-only prep on s_prep
    cudaEventRecord(ev_fork, 0);
    cudaStreamWaitEvent(s_prep, ev_fork, 0);
    pack_w_kernel<<<dim3(64, N_CONV), 256, 0, s_prep>>>(conv_w);
    build_tab_kernel<<<dim3(N_T, N_CONV), 256, 0, s_prep>>>(conv_w);
    expand_tab_kernel<<<dim3(NTF, N_CONV), 256, 0, s_prep>>>();
    cudaEventRecord(ev_join, s_prep);

    // main chain: setup (zero + emb table + graph counts), gather+hist, sort
    setup_kernel<<<SGRID + 101, SB>>>(embedding, emb_w, emb_b, batch);
    gather_hist_kernel<<<GHGRID, SB>>>(z, dst);
    scan_pass1<<<SGRID, SB>>>();
    scan_pass2<<<1, SB>>>();
    scan_pass3<<<SGRID, SB>>>();
    scatter_kernel<<<(N_EDGES + 255) / 256, 256>>>(R, src, dst);

    // join prep before conv layers
    cudaStreamWaitEvent(0, ev_join, 0);

    for (int l = 0; l < N_CONV; l++) {
        const float* bl = conv_b + (size_t)l * 256;
        dim3 ggrid(2, (N_NODES + TBM - 1) / TBM);
        gemm_mma_kernel<<<ggrid, 256>>>(bl, l);
        if (l < N_CONV - 1)
            edge_agg_kernel<false><<<N_NODES, 64>>>(
                ln_g + l * NODE_D, ln_b + l * NODE_D, batch, l);
        else
            edge_agg_kernel<true><<<N_NODES, 64>>>(
                ln_g + l * NODE_D, ln_b + l * NODE_D, batch, l);
    }

    head_kernel<<<N_GRAPHS, FC_D>>>(cfc_w, cfc_b, fc_w, fc_b, out_w, out_b, out);
}